// round 8
// baseline (speedup 1.0000x reference)
#include <cuda_runtime.h>
#include <cuda_bf16.h>

// ODE-GRU: B=128, L=2048, I=D=64.
// Round 8: R5 structure (proven fastest) + 2 independent batch sequences per
// CTA. 64 CTAs x 256 threads. Weights register-resident (2 rows/thread,
// packed f32x2); every phase computes DUAL dots (same weights, two batches'
// vectors) -> 8 independent FMA chains, latency of the serial phase chain
// amortized over 2 sequences. 4 barriers per (dual) step.

#define NB 128
#define NL 2048
#define ND 64
#define NG 192

typedef unsigned long long u64;

__device__ __forceinline__ u64 fma2(u64 a, u64 b, u64 c) {
    u64 d;
    asm("fma.rn.f32x2 %0, %1, %2, %3;" : "=l"(d) : "l"(a), "l"(b), "l"(c));
    return d;
}
__device__ __forceinline__ u64 add2(u64 a, u64 b) {
    u64 d;
    asm("add.rn.f32x2 %0, %1, %2;" : "=l"(d) : "l"(a), "l"(b));
    return d;
}
__device__ __forceinline__ u64 pk(float lo, float hi) {
    u64 r;
    asm("mov.b64 %0, {%1, %2};" : "=l"(r) : "f"(lo), "f"(hi));
    return r;
}

// Dual dot: same packed weight row against two different 64-vectors.
// 8 independent FFMA2 chains (4 per batch) -> high ILP to cover lat=4.
__device__ __forceinline__ float2 dot64p_dual(const u64* __restrict__ w,
                                              const float* __restrict__ va,
                                              const float* __restrict__ vb,
                                              float bias)
{
    const ulonglong2* __restrict__ a2 = (const ulonglong2*)va;
    const ulonglong2* __restrict__ b2 = (const ulonglong2*)vb;
    u64 x0 = pk(bias, 0.f), x1 = 0ull, x2 = 0ull, x3 = 0ull;
    u64 y0 = pk(bias, 0.f), y1 = 0ull, y2 = 0ull, y3 = 0ull;
#pragma unroll
    for (int q = 0; q < 8; q++) {
        ulonglong2 pa = a2[2*q];
        ulonglong2 ra = a2[2*q + 1];
        ulonglong2 pb = b2[2*q];
        ulonglong2 rb = b2[2*q + 1];
        u64 w0 = w[4*q+0], w1 = w[4*q+1], w2 = w[4*q+2], w3 = w[4*q+3];
        x0 = fma2(w0, pa.x, x0);  y0 = fma2(w0, pb.x, y0);
        x1 = fma2(w1, pa.y, x1);  y1 = fma2(w1, pb.y, y1);
        x2 = fma2(w2, ra.x, x2);  y2 = fma2(w2, rb.x, y2);
        x3 = fma2(w3, ra.y, x3);  y3 = fma2(w3, rb.y, y3);
    }
    u64 sx = add2(add2(x0, x1), add2(x2, x3));
    u64 sy = add2(add2(y0, y1), add2(y2, y3));
    float2 r;
    r.x = __uint_as_float((unsigned)sx) + __uint_as_float((unsigned)(sx >> 32));
    r.y = __uint_as_float((unsigned)sy) + __uint_as_float((unsigned)(sy >> 32));
    return r;
}

__device__ __forceinline__ float sigmoidf_(float a) {
    return __fdividef(1.f, 1.f + __expf(-a));
}
__device__ __forceinline__ float tanhf_fast(float x) {
    float e = __expf(2.f * x);
    return 1.f - __fdividef(2.f, e + 1.f);
}

__global__ __launch_bounds__(256, 1)
void odegru_kernel(const float* __restrict__ x,
                   const float* __restrict__ tdel,
                   const int*   __restrict__ seq,
                   const float* __restrict__ h0,
                   const float* __restrict__ w_ih,
                   const float* __restrict__ w_hh,
                   const float* __restrict__ b_ih,
                   const float* __restrict__ b_hh,
                   const float* __restrict__ dw1,
                   const float* __restrict__ db1,
                   const float* __restrict__ dw2,
                   const float* __restrict__ db2,
                   float* __restrict__ out)
{
    const int b0  = 2 * blockIdx.x;       // this CTA's two batches
    const int b1  = b0 + 1;
    const int tid = threadIdx.x;

    __shared__ __align__(16) float sh_h[2][ND];
    __shared__ __align__(16) float sh_t1[2][ND];
    __shared__ __align__(16) float sh_ho[2][ND];
    __shared__ __align__(16) float sh_gx[2][NG];
    __shared__ __align__(16) float sh_gh[2][128];  // rows 0..127 (128+j in reg)
    __shared__ __align__(16) float sh_x[2][2][ND]; // [batch][buf][j]
    __shared__ float sh_dt[2][2];                  // [batch][buf]

    // ---- packed weight rows (2 per thread), identical role split to R5 ----
    // thr   0- 63: wX = dw1 row j        (P1)   wY = w_hh row 128+j (P3)
    // thr  64-127: wX = dw2 row j        (P2)   wY = w_ih row j     (P1)
    // thr 128-255: wX = w_hh row tid-128 (P3)   wY = w_ih row tid-64(P1)
    u64 wX[32], wY[32];
    float bX, bY;
    const float* pX;
    const float* pY;
    if (tid < 64) {
        pX = dw1 + tid * 64;          bX = db1[tid];
        pY = w_hh + (128 + tid) * 64; bY = b_hh[128 + tid];
    } else if (tid < 128) {
        int j = tid - 64;
        pX = dw2 + j * 64;            bX = db2[j];
        pY = w_ih + j * 64;           bY = b_ih[j];
    } else {
        pX = w_hh + (tid - 128) * 64; bX = b_hh[tid - 128];
        pY = w_ih + (tid - 64) * 64;  bY = b_ih[tid - 64];
    }
#pragma unroll
    for (int k = 0; k < 32; k++) {
        wX[k] = ((const u64*)pX)[k];
        wY[k] = ((const u64*)pY)[k];
    }

    const int sl0 = seq[b0];
    const int sl1 = seq[b1];
    const float* xb0  = x + (size_t)b0 * NL * ND;
    const float* xb1  = x + (size_t)b1 * NL * ND;
    const float* dtb0 = tdel + (size_t)b0 * NL;
    const float* dtb1 = tdel + (size_t)b1 * NL;
    float* outb0 = out + (size_t)b0 * NL * ND;
    float* outb1 = out + (size_t)b1 * NL * ND;

    if (tid < 64) {
        float h = h0[tid];
        sh_h[0][tid] = h;
        sh_h[1][tid] = h;
        sh_x[0][0][tid] = xb0[tid];    // t=0 always live (sl >= 1)
        sh_x[1][0][tid] = xb1[tid];
    }
    if (tid == 64) { sh_dt[0][0] = dtb0[0]; sh_dt[1][0] = dtb1[0]; }

    float fin0 = 0.f, fin1 = 0.f;
    __syncthreads();

    for (int t = 0; t < NL; t++) {
        const int cur = t & 1, nxt = cur ^ 1;
        const int tn  = t + 1;

        // prefetch x/dt for step t+1 (committed in P4)
        float xr0 = 0.f, xr1 = 0.f, dtr0 = 0.f, dtr1 = 0.f;
        if (tn < NL) {
            if (tid < 64) {
                xr0 = xb0[(size_t)tn * ND + tid];
                xr1 = xb1[(size_t)tn * ND + tid];
            }
            if (tid == 64) { dtr0 = dtb0[tn]; dtr1 = dtb1[tn]; }
        }

        // ---- P1: t1 = tanh(h*dw1^T+db1)  ||  gx = x_t*w_ih^T+b_ih ----
        if (tid < 64) {
            float2 u = dot64p_dual(wX, sh_h[0], sh_h[1], bX);
            sh_t1[0][tid] = tanhf_fast(u.x);
            sh_t1[1][tid] = tanhf_fast(u.y);
        } else {
            float2 g = dot64p_dual(wY, sh_x[0][cur], sh_x[1][cur], bY);
            sh_gx[0][tid - 64] = g.x;
            sh_gx[1][tid - 64] = g.y;
        }
        __syncthreads();

        // ---- P2: d = t1*dw2^T+db2;  h_ode = h + d*dt ----
        if (tid >= 64 && tid < 128) {
            int j = tid - 64;
            float2 d = dot64p_dual(wX, sh_t1[0], sh_t1[1], bX);
            sh_ho[0][j] = fmaf(d.x, sh_dt[0][cur], sh_h[0][j]);
            sh_ho[1][j] = fmaf(d.y, sh_dt[1][cur], sh_h[1][j]);
        }
        __syncthreads();

        // ---- P3: gh = h_ode*w_hh^T + b_hh ----
        float gn0 = 0.f, gn1 = 0.f;        // gh[128+j], kept by thread j
        if (tid < 64) {
            float2 g = dot64p_dual(wY, sh_ho[0], sh_ho[1], bY);
            gn0 = g.x; gn1 = g.y;
        } else if (tid >= 128) {
            float2 g = dot64p_dual(wX, sh_ho[0], sh_ho[1], bX);
            sh_gh[0][tid - 128] = g.x;
            sh_gh[1][tid - 128] = g.y;
        }
        __syncthreads();

        // ---- P4: gates for both batches + prefetch commit ----
        if (tid < 64) {
            const int j = tid;
            {   // batch 0
                float r  = sigmoidf_(sh_gx[0][j]      + sh_gh[0][j]);
                float z  = sigmoidf_(sh_gx[0][64 + j] + sh_gh[0][64 + j]);
                float n  = tanhf_fast(fmaf(r, gn0, sh_gx[0][128 + j]));
                float ho = sh_ho[0][j];
                float hn = fmaf(z, ho - n, n);
                sh_h[0][j] = hn;
                outb0[(size_t)t * ND + j] = hn;
                if (t == sl0 - 1) fin0 = hn;
                sh_x[0][nxt][j] = (tn < sl0) ? xr0 : 0.f;
            }
            {   // batch 1
                float r  = sigmoidf_(sh_gx[1][j]      + sh_gh[1][j]);
                float z  = sigmoidf_(sh_gx[1][64 + j] + sh_gh[1][64 + j]);
                float n  = tanhf_fast(fmaf(r, gn1, sh_gx[1][128 + j]));
                float ho = sh_ho[1][j];
                float hn = fmaf(z, ho - n, n);
                sh_h[1][j] = hn;
                outb1[(size_t)t * ND + j] = hn;
                if (t == sl1 - 1) fin1 = hn;
                sh_x[1][nxt][j] = (tn < sl1) ? xr1 : 0.f;
            }
        }
        if (tid == 64) {
            sh_dt[0][nxt] = (tn < sl0) ? dtr0 : 0.f;
            sh_dt[1][nxt] = (tn < sl1) ? dtr1 : 0.f;
        }
        __syncthreads();
    }

    // final hidden states -> second output tensor (1, B, D)
    if (tid < 64) {
        out[(size_t)NB * NL * ND + (size_t)b0 * ND + tid] = fin0;
        out[(size_t)NB * NL * ND + (size_t)b1 * ND + tid] = fin1;
    }
}

extern "C" void kernel_launch(void* const* d_in, const int* in_sizes, int n_in,
                              void* d_out, int out_size)
{
    const float* x    = (const float*)d_in[0];
    const float* tdel = (const float*)d_in[1];
    const int*   seq  = (const int*)  d_in[2];
    const float* h0   = (const float*)d_in[3];
    const float* w_ih = (const float*)d_in[4];
    const float* w_hh = (const float*)d_in[5];
    const float* b_ih = (const float*)d_in[6];
    const float* b_hh = (const float*)d_in[7];
    const float* dw1  = (const float*)d_in[8];
    const float* db1  = (const float*)d_in[9];
    const float* dw2  = (const float*)d_in[10];
    const float* db2  = (const float*)d_in[11];

    odegru_kernel<<<NB / 2, 256>>>(x, tdel, seq, h0, w_ih, w_hh, b_ih, b_hh,
                                   dw1, db1, dw2, db2, (float*)d_out);
}

// round 9
// speedup vs baseline: 1.5109x; 1.5109x over previous
#include <cuda_runtime.h>
#include <cuda_bf16.h>

// ODE-GRU: B=128, L=2048, I=D=64.
// Round 9: R5 phase structure + dot count (512 dots/step, the minimum), but
// 512 threads/CTA: every 64-dot is split across a lane pair (l, l+16) in one
// warp (halves [0:32)/[32:64)), combined with one shfl.bfly(16). Doubles the
// eligible warps/SMSP in the GEMV phases (latency hiding) at identical issue
// work, and halves weight-register pressure (64 regs) -> no spills at 512thr.
//   P1: t1 (warps 0-3) || gx (warps 4-15)
//   P2: h_ode (warps 0-3) || x/dt prefetch LDG (warps 4-6)
//   P3: gh (warps 4-15)
//   P4: gates (64 lanes) + prefetch commit

#define NB 128
#define NL 2048
#define ND 64
#define NG 192
#define NT 512

typedef unsigned long long u64;

__device__ __forceinline__ u64 fma2(u64 a, u64 b, u64 c) {
    u64 d;
    asm("fma.rn.f32x2 %0, %1, %2, %3;" : "=l"(d) : "l"(a), "l"(b), "l"(c));
    return d;
}
__device__ __forceinline__ u64 add2(u64 a, u64 b) {
    u64 d;
    asm("add.rn.f32x2 %0, %1, %2;" : "=l"(d) : "l"(a), "l"(b));
    return d;
}

// half-dot: 32 elements of v starting at off, against pre-packed half-row w.
__device__ __forceinline__ float dot32p(const u64* __restrict__ w,
                                        const float* __restrict__ v,
                                        int off)
{
    const ulonglong2* __restrict__ v2 = (const ulonglong2*)(v + off);
    u64 a0 = 0ull, a1 = 0ull, a2 = 0ull, a3 = 0ull;
#pragma unroll
    for (int q = 0; q < 4; q++) {
        ulonglong2 p = v2[2*q];
        ulonglong2 r = v2[2*q + 1];
        a0 = fma2(w[4*q+0], p.x, a0);
        a1 = fma2(w[4*q+1], p.y, a1);
        a2 = fma2(w[4*q+2], r.x, a2);
        a3 = fma2(w[4*q+3], r.y, a3);
    }
    u64 s = add2(add2(a0, a1), add2(a2, a3));
    return __uint_as_float((unsigned)s) + __uint_as_float((unsigned)(s >> 32));
}

__device__ __forceinline__ float sigmoidf_(float a) {
    return __fdividef(1.f, 1.f + __expf(-a));
}
__device__ __forceinline__ float tanhf_fast(float x) {
    float e = __expf(2.f * x);
    return 1.f - __fdividef(2.f, e + 1.f);
}

__global__ __launch_bounds__(NT, 1)
void odegru_kernel(const float* __restrict__ x,
                   const float* __restrict__ tdel,
                   const int*   __restrict__ seq,
                   const float* __restrict__ h0,
                   const float* __restrict__ w_ih,
                   const float* __restrict__ w_hh,
                   const float* __restrict__ b_ih,
                   const float* __restrict__ b_hh,
                   const float* __restrict__ dw1,
                   const float* __restrict__ db1,
                   const float* __restrict__ dw2,
                   const float* __restrict__ db2,
                   float* __restrict__ out)
{
    const int b    = blockIdx.x;
    const int tid  = threadIdx.x;
    const int w    = tid >> 5;
    const int l    = tid & 31;
    const int sub  = l & 15;        // row within warp's 16-row block
    const int off  = (l >> 4) << 5; // element offset: 0 or 32
    const bool wr  = (l < 16);      // writer lane for this row

    __shared__ __align__(16) float sh_h[ND];
    __shared__ __align__(16) float sh_t1[ND];
    __shared__ __align__(16) float sh_ho[ND];
    __shared__ __align__(16) float sh_gx[NG];
    __shared__ __align__(16) float sh_gh[NG];
    __shared__ __align__(16) float sh_x[2][ND];
    __shared__ float sh_dt[2];

    // ---- packed half-rows (16 u64 each) ----
    // warps 0-3 : P-role = dw1 row r16 (P1->t1), Q-role = dw2 row r16 (P2)
    // warps 4-15: P-role = w_ih row r16 (P1->gx), Q-role = w_hh row r16 (P3)
    const int r16 = (w < 4 ? w * 16 : (w - 4) * 16) + sub;
    u64 wP[16], wQ[16];
    float bP, bQ;
    {
        const float *pP, *pQ;
        if (w < 4) { pP = dw1 + r16 * ND;  bP = db1[r16];
                     pQ = dw2 + r16 * ND;  bQ = db2[r16]; }
        else       { pP = w_ih + r16 * ND; bP = b_ih[r16];
                     pQ = w_hh + r16 * ND; bQ = b_hh[r16]; }
        const u64* uP = (const u64*)(pP + off);
        const u64* uQ = (const u64*)(pQ + off);
#pragma unroll
        for (int k = 0; k < 16; k++) { wP[k] = uP[k]; wQ[k] = uQ[k]; }
    }

    const int sl = seq[b];
    const float* xb  = x + (size_t)b * NL * ND;
    const float* dtb = tdel + (size_t)b * NL;
    float* outb      = out + (size_t)b * NL * ND;

    if (tid < 64) {
        sh_h[tid]    = h0[tid];
        sh_x[0][tid] = xb[tid];        // t=0 always live (sl >= 1)
    }
    if (tid == 192) sh_dt[0] = dtb[0];

    float fin = 0.f;
    float xr = 0.f, dtr = 0.f;
    __syncthreads();

    for (int t = 0; t < NL; t++) {
        const int cur = t & 1, nxt = cur ^ 1;
        const int tn  = t + 1;

        // ---- P1: t1 = tanh(h*dw1^T+db1) || gx = x_t*w_ih^T+b_ih ----
        if (w < 4) {
            float u = dot32p(wP, sh_h, off);
            u += __shfl_xor_sync(0xffffffffu, u, 16);
            if (wr) sh_t1[r16] = tanhf_fast(u + bP);
        } else {
            float g = dot32p(wP, sh_x[cur], off);
            g += __shfl_xor_sync(0xffffffffu, g, 16);
            if (wr) sh_gx[r16] = g + bP;
        }
        __syncthreads();

        // ---- P2: h_ode = h + (t1*dw2^T+db2)*dt  || x/dt prefetch LDG ----
        if (w < 4) {
            float d = dot32p(wQ, sh_t1, off);
            d += __shfl_xor_sync(0xffffffffu, d, 16);
            if (wr) sh_ho[r16] = fmaf(d + bQ, sh_dt[cur], sh_h[r16]);
        } else if (tid >= 128 && tid < 192) {
            if (tn < NL) xr = xb[(size_t)tn * ND + (tid - 128)];
        } else if (tid == 192) {
            if (tn < NL) dtr = dtb[tn];
        }
        __syncthreads();

        // ---- P3: gh = h_ode*w_hh^T + b_hh ----
        if (w >= 4) {
            float g = dot32p(wQ, sh_ho, off);
            g += __shfl_xor_sync(0xffffffffu, g, 16);
            if (wr) sh_gh[r16] = g + bQ;
        }
        __syncthreads();

        // ---- P4: gates (64 lanes) + prefetch commit ----
        if (tid < 64) {
            const int j = tid;
            float r  = sigmoidf_(sh_gx[j]      + sh_gh[j]);
            float z  = sigmoidf_(sh_gx[64 + j] + sh_gh[64 + j]);
            float n  = tanhf_fast(fmaf(r, sh_gh[128 + j], sh_gx[128 + j]));
            float ho = sh_ho[j];
            float hn = fmaf(z, ho - n, n);     // (1-z)*n + z*ho
            sh_h[j] = hn;
            outb[(size_t)t * ND + j] = hn;
            if (t == sl - 1) fin = hn;
        } else if (tid >= 128 && tid < 192) {
            sh_x[nxt][tid - 128] = (tn < sl) ? xr : 0.f;  // PaddedBatch mask
        } else if (tid == 192) {
            sh_dt[nxt] = (tn < sl) ? dtr : 0.f;
        }
        __syncthreads();
    }

    // final hidden state -> second output tensor (1, B, D)
    if (tid < 64)
        out[(size_t)NB * NL * ND + (size_t)b * ND + tid] = fin;
}

extern "C" void kernel_launch(void* const* d_in, const int* in_sizes, int n_in,
                              void* d_out, int out_size)
{
    const float* x    = (const float*)d_in[0];
    const float* tdel = (const float*)d_in[1];
    const int*   seq  = (const int*)  d_in[2];
    const float* h0   = (const float*)d_in[3];
    const float* w_ih = (const float*)d_in[4];
    const float* w_hh = (const float*)d_in[5];
    const float* b_ih = (const float*)d_in[6];
    const float* b_hh = (const float*)d_in[7];
    const float* dw1  = (const float*)d_in[8];
    const float* db1  = (const float*)d_in[9];
    const float* dw2  = (const float*)d_in[10];
    const float* db2  = (const float*)d_in[11];

    odegru_kernel<<<NB, NT>>>(x, tdel, seq, h0, w_ih, w_hh, b_ih, b_hh,
                              dw1, db1, dw2, db2, (float*)d_out);
}